// round 7
// baseline (speedup 1.0000x reference)
#include <cuda_runtime.h>
#include <cstdint>

#define N_NODES 100000
#define N_EDGES 1600000
#define IN_F    128
#define OUT_F   32

// Scratch (__device__ globals; no allocation anywhere in this file).
__device__ int   g_deg[N_NODES];
__device__ float g_dis[N_NODES];
__device__ float g_hs [N_NODES * OUT_F];   // h * dis[node]  (pre-scaled by src norm)
__device__ float g_acc[N_NODES * OUT_F];   // aggregation accumulator

// ---------------------------------------------------------------------------
__global__ void k_deg_init() {
    int i = blockIdx.x * blockDim.x + threadIdx.x;
    if (i < N_NODES) g_deg[i] = 1;                 // self loop
}

__global__ void k_deg_count(const int* __restrict__ ei) {
    int e = blockIdx.x * blockDim.x + threadIdx.x;
    if (e < N_EDGES) atomicAdd(&g_deg[ei[N_EDGES + e]], 1);
}

__global__ void k_dis() {
    int i = blockIdx.x * blockDim.x + threadIdx.x;
    if (i < N_NODES) g_dis[i] = rsqrtf((float)g_deg[i]);
}

// ---------------------------------------------------------------------------
// K4: h = x @ W^T via packed f32x2 FMA (FFMA2).
// Pairing over k: double2 loads of x give (x[k],x[k+1]) bit-packed for free;
// W pre-packed in shared as 64-bit (w[k],w[k+1]) per out-feature.
// 256 threads = 8 warps; warp register-blocks 8 nodes; lane = out feature.
#define NODES_PER_WARP 8
#define NODES_PER_BLK  64
#define FFMA2(acc, a, b) \
    asm("fma.rn.f32x2 %0, %1, %2, %0;" : "+l"(acc) : "l"(a), "l"(b))

__global__ __launch_bounds__(256) void k_linear(const float* __restrict__ x,
                                                const float* __restrict__ W) {
    __shared__ unsigned long long sW2[IN_F / 2][OUT_F];   // [k2][f] = (w[2k2],w[2k2+1])

    int tid = threadIdx.x;
    // W is [OUT_F][IN_F] row-major -> float2 view [OUT_F][64], coalesced loads.
    const float2* W2 = (const float2*)W;
    #pragma unroll
    for (int i = 0; i < 8; i++) {                   // 2048 float2 / 256 threads
        int idx = tid + i * 256;
        int f  = idx >> 6;                          // / 64
        int k2 = idx & 63;
        float2 w = W2[idx];
        sW2[k2][f] = ((unsigned long long)__float_as_uint(w.y) << 32)
                   |  (unsigned long long)__float_as_uint(w.x);
    }
    __syncthreads();

    int warp = tid >> 5;
    int f    = tid & 31;
    int node_base = blockIdx.x * NODES_PER_BLK + warp * NODES_PER_WARP;

    const double2* xr[NODES_PER_WARP];
    #pragma unroll
    for (int n = 0; n < NODES_PER_WARP; n++) {
        int nc = node_base + n;
        if (nc > N_NODES - 1) nc = N_NODES - 1;     // tail clamp; store guarded
        xr[n] = (const double2*)(x + (size_t)nc * IN_F);
    }

    unsigned long long acc2[NODES_PER_WARP];        // packed (even-k sum, odd-k sum)
    #pragma unroll
    for (int n = 0; n < NODES_PER_WARP; n++) acc2[n] = 0ull;

    #pragma unroll 4
    for (int k4 = 0; k4 < IN_F / 4; k4++) {
        unsigned long long w0 = sW2[2 * k4 + 0][f];
        unsigned long long w1 = sW2[2 * k4 + 1][f];
        #pragma unroll
        for (int n = 0; n < NODES_PER_WARP; n++) {
            double2 d = xr[n][k4];                  // broadcast LDG.128, pre-packed pairs
            unsigned long long a0 = __double_as_longlong(d.x);
            unsigned long long a1 = __double_as_longlong(d.y);
            FFMA2(acc2[n], a0, w0);
            FFMA2(acc2[n], a1, w1);
        }
    }

    #pragma unroll
    for (int n = 0; n < NODES_PER_WARP; n++) {
        int node = node_base + n;
        if (node < N_NODES) {
            float lo = __uint_as_float((unsigned)(acc2[n] & 0xFFFFFFFFull));
            float hi = __uint_as_float((unsigned)(acc2[n] >> 32));
            float h  = lo + hi;
            float d  = g_dis[node];
            g_hs [node * OUT_F + f] = h * d;
            g_acc[node * OUT_F + f] = h * d * d;    // self-loop term
        }
    }
}

// ---------------------------------------------------------------------------
// K5: edge scatter. 8 lanes per edge; float4 gather + red.global.v4.f32.
__global__ __launch_bounds__(256) void k_scatter(const int* __restrict__ ei) {
    int gtid = blockIdx.x * blockDim.x + threadIdx.x;
    int e  = gtid >> 3;
    int fq = (gtid & 7) * 4;

    int src = ei[e];
    int dst = ei[N_EDGES + e];

    float nd = g_dis[dst];
    float4 h = *(const float4*)(g_hs + src * OUT_F + fq);   // coalesced 128B/edge
    float4 v = make_float4(h.x * nd, h.y * nd, h.z * nd, h.w * nd);

    float* a = g_acc + dst * OUT_F + fq;
    asm volatile("red.global.add.v4.f32 [%0], {%1, %2, %3, %4};"
                 :: "l"(a), "f"(v.x), "f"(v.y), "f"(v.z), "f"(v.w)
                 : "memory");
}

// ---------------------------------------------------------------------------
// K6: out = g_acc + b   (plain coalesced float4 stores only touch d_out)
__global__ __launch_bounds__(256) void k_finalize(const float* __restrict__ b,
                                                  float* __restrict__ out) {
    int i = blockIdx.x * blockDim.x + threadIdx.x;    // float4 index
    if (i < N_NODES * OUT_F / 4) {
        float4 a = *((const float4*)g_acc + i);
        int fb = (i * 4) & (OUT_F - 1);
        a.x += b[fb + 0]; a.y += b[fb + 1]; a.z += b[fb + 2]; a.w += b[fb + 3];
        *((float4*)out + i) = a;
    }
}

// ---------------------------------------------------------------------------
extern "C" void kernel_launch(void* const* d_in, const int* in_sizes, int n_in,
                              void* d_out, int out_size) {
    const float* x  = (const float*)d_in[0];
    const int*   ei = (const int*)d_in[1];     // int32 (harness downcasts int64)
    const float* W  = (const float*)d_in[2];
    const float* b  = (const float*)d_in[3];
    float*       out = (float*)d_out;

    (void)in_sizes; (void)n_in; (void)out_size;

    k_deg_init <<<(N_NODES + 255) / 256, 256>>>();
    k_deg_count<<<(N_EDGES + 255) / 256, 256>>>(ei);
    k_dis      <<<(N_NODES + 255) / 256, 256>>>();
    k_linear   <<<(N_NODES + NODES_PER_BLK - 1) / NODES_PER_BLK, 256>>>(x, W);
    k_scatter  <<<(N_EDGES * 8) / 256, 256>>>(ei);
    k_finalize <<<(N_NODES * OUT_F / 4 + 255) / 256, 256>>>(b, out);
}

// round 8
// speedup vs baseline: 1.2008x; 1.2008x over previous
#include <cuda_runtime.h>
#include <cstdint>

#define N_NODES 100000
#define N_EDGES 1600000
#define IN_F    128
#define OUT_F   32

// Scratch (__device__ globals; no allocation anywhere in this file).
__device__ int   g_deg[N_NODES];
__device__ float g_hs [N_NODES * OUT_F];   // h * dis[node]  (src-normalized message)
__device__ float g_acc[N_NODES * OUT_F];   // accumulator (init = self-loop term h*dis)

// ---------------------------------------------------------------------------
__global__ void k_deg_init() {
    int i = blockIdx.x * blockDim.x + threadIdx.x;
    if (i < N_NODES) g_deg[i] = 1;                 // self loop
}

__global__ void k_deg_count(const int* __restrict__ ei) {
    int e = blockIdx.x * blockDim.x + threadIdx.x;
    if (e < N_EDGES) atomicAdd(&g_deg[ei[N_EDGES + e]], 1);
}

// ---------------------------------------------------------------------------
// K4: h = x @ W^T ; g_hs = g_acc = h * rsqrt(deg).
// x staged through shared (coalesced float4) -> broadcast LDS in mainloop.
// 256 threads = 8 warps; warp register-blocks 8 nodes; lane = out feature.
#define NODES_PER_WARP 8
#define NODES_PER_BLK  64
__global__ __launch_bounds__(256) void k_linear(const float* __restrict__ x,
                                                const float* __restrict__ W) {
    __shared__ float sWt[IN_F][OUT_F];              // [k][f]; compute reads conflict-free
    __shared__ float sx[NODES_PER_BLK][IN_F];       // 32KB tile (total 48KB static)

    int tid = threadIdx.x;

    // W load: f = tid&31, k = idx>>5 -> STS conflict-free (lanes write k*32+f).
    // (W global read is strided but W is 16KB and L2-resident.)
    #pragma unroll
    for (int i = 0; i < 16; i++) {                  // 4096 elems / 256 threads
        int idx = tid + i * 256;
        int f = idx & 31;
        int k = idx >> 5;
        sWt[k][f] = W[f * IN_F + k];
    }

    // Stage 64 node rows of x: 2048 float4, fully coalesced.
    int node0 = blockIdx.x * NODES_PER_BLK;
    const float4* xg = (const float4*)(x + (size_t)node0 * IN_F);
    float4* sx4 = (float4*)sx;
    bool full = (node0 + NODES_PER_BLK <= N_NODES);
    #pragma unroll
    for (int i = 0; i < 8; i++) {
        int idx = tid + i * 256;                    // float4 index in tile
        if (full || node0 + (idx >> 5) < N_NODES)
            sx4[idx] = xg[idx];
        else
            sx4[idx] = make_float4(0.f, 0.f, 0.f, 0.f);
    }
    __syncthreads();

    int warp = tid >> 5;
    int f    = tid & 31;
    int nb   = warp * NODES_PER_WARP;               // local node base

    float acc[NODES_PER_WARP];
    #pragma unroll
    for (int n = 0; n < NODES_PER_WARP; n++) acc[n] = 0.0f;

    #pragma unroll 8
    for (int k4 = 0; k4 < IN_F / 4; k4++) {
        int k = k4 * 4;
        float w0 = sWt[k + 0][f];
        float w1 = sWt[k + 1][f];
        float w2 = sWt[k + 2][f];
        float w3 = sWt[k + 3][f];
        #pragma unroll
        for (int n = 0; n < NODES_PER_WARP; n++) {
            float4 xv = *(const float4*)&sx[nb + n][k];   // broadcast LDS.128
            acc[n] = fmaf(xv.x, w0, acc[n]);
            acc[n] = fmaf(xv.y, w1, acc[n]);
            acc[n] = fmaf(xv.z, w2, acc[n]);
            acc[n] = fmaf(xv.w, w3, acc[n]);
        }
    }

    #pragma unroll
    for (int n = 0; n < NODES_PER_WARP; n++) {
        int node = node0 + nb + n;
        if (node < N_NODES) {
            float d  = rsqrtf((float)g_deg[node]);
            float hd = acc[n] * d;
            g_hs [node * OUT_F + f] = hd;
            g_acc[node * OUT_F + f] = hd;           // self-loop term (dis folded at finalize)
        }
    }
}

// ---------------------------------------------------------------------------
// K5: edge scatter. 8 lanes per edge; pure gather + RED (dst norm hoisted out).
__global__ __launch_bounds__(256) void k_scatter(const int* __restrict__ ei) {
    int gtid = blockIdx.x * blockDim.x + threadIdx.x;
    int e  = gtid >> 3;
    int fq = (gtid & 7) * 4;

    int src = ei[e];
    int dst = ei[N_EDGES + e];

    float4 v = *(const float4*)(g_hs + src * OUT_F + fq);   // coalesced 128B/edge
    float* a = g_acc + dst * OUT_F + fq;
    asm volatile("red.global.add.v4.f32 [%0], {%1, %2, %3, %4};"
                 :: "l"(a), "f"(v.x), "f"(v.y), "f"(v.z), "f"(v.w)
                 : "memory");
}

// ---------------------------------------------------------------------------
// K6: out = g_acc * dis[node] + b   (plain coalesced float4 stores to d_out)
__global__ __launch_bounds__(256) void k_finalize(const float* __restrict__ b,
                                                  float* __restrict__ out) {
    int i = blockIdx.x * blockDim.x + threadIdx.x;    // float4 index
    if (i < N_NODES * OUT_F / 4) {
        int node = i >> 3;                            // 8 quads per node
        float d  = rsqrtf((float)g_deg[node]);
        float4 a = *((const float4*)g_acc + i);
        int fb = (i * 4) & (OUT_F - 1);
        a.x = fmaf(a.x, d, b[fb + 0]);
        a.y = fmaf(a.y, d, b[fb + 1]);
        a.z = fmaf(a.z, d, b[fb + 2]);
        a.w = fmaf(a.w, d, b[fb + 3]);
        *((float4*)out + i) = a;
    }
}

// ---------------------------------------------------------------------------
extern "C" void kernel_launch(void* const* d_in, const int* in_sizes, int n_in,
                              void* d_out, int out_size) {
    const float* x  = (const float*)d_in[0];
    const int*   ei = (const int*)d_in[1];     // int32 (harness downcasts int64)
    const float* W  = (const float*)d_in[2];
    const float* b  = (const float*)d_in[3];
    float*       out = (float*)d_out;

    (void)in_sizes; (void)n_in; (void)out_size;

    k_deg_init <<<(N_NODES + 255) / 256, 256>>>();
    k_deg_count<<<(N_EDGES + 255) / 256, 256>>>(ei);
    k_linear   <<<(N_NODES + NODES_PER_BLK - 1) / NODES_PER_BLK, 256>>>(x, W);
    k_scatter  <<<(N_EDGES * 8) / 256, 256>>>(ei);
    k_finalize <<<(N_NODES * OUT_F / 4 + 255) / 256, 256>>>(b, out);
}